// round 15
// baseline (speedup 1.0000x reference)
#include <cuda_runtime.h>
#include <cuda_fp16.h>
#include <cstdint>
#include <math.h>

#define NTOK 81920
#define DMODEL 512
#define DFF 2048
#define NH 8
#define HD 64
#define CTXT 20
#define NB 4096
#define QKVC 1536

// ---------------- scratch ----------------
__device__ __half g_qkvh[(size_t)NTOK * QKVC];
__device__ float g_x2[(size_t)NTOK * DMODEL];
__device__ __half g_hh[(size_t)NTOK * DMODEL];
__device__ __half g_ch[(size_t)NTOK * DMODEL];
__device__ __half g_uh[(size_t)NTOK * DFF];
// packed weights: [N][K] fp16
__device__ __half g_bqkv[QKVC * DMODEL];
__device__ __half g_bo[DMODEL * DMODEL];
__device__ __half g_b1w[DFF * DMODEL];
__device__ __half g_b2w[DMODEL * DFF];

// ---------------- helpers ----------------
__device__ __forceinline__ uint32_t smem_to_u32(const void* p) {
    uint32_t a;
    asm("{ .reg .u64 t; cvta.to.shared.u64 t, %1; cvt.u32.u64 %0, t; }" : "=r"(a) : "l"(p));
    return a;
}
#define CP_ASYNC16(dst, src) \
    asm volatile("cp.async.cg.shared.global [%0], [%1], 16;" :: "r"(dst), "l"(src))
#define CP_COMMIT() asm volatile("cp.async.commit_group;")
#define CP_WAIT1()  asm volatile("cp.async.wait_group 1;")

__device__ __forceinline__ void ldsm4(uint32_t& r0, uint32_t& r1, uint32_t& r2, uint32_t& r3,
                                      uint32_t addr) {
    asm volatile("ldmatrix.sync.aligned.m8n8.x4.shared.b16 {%0,%1,%2,%3}, [%4];"
                 : "=r"(r0), "=r"(r1), "=r"(r2), "=r"(r3) : "r"(addr));
}
__device__ __forceinline__ void mma16816(float* c, uint32_t a0, uint32_t a1, uint32_t a2,
                                         uint32_t a3, uint32_t b0, uint32_t b1) {
    asm volatile(
        "mma.sync.aligned.m16n8k16.row.col.f32.f16.f16.f32 "
        "{%0,%1,%2,%3}, {%4,%5,%6,%7}, {%8,%9}, {%0,%1,%2,%3};"
        : "+f"(c[0]), "+f"(c[1]), "+f"(c[2]), "+f"(c[3])
        : "r"(a0), "r"(a1), "r"(a2), "r"(a3), "r"(b0), "r"(b1));
}

// ---------------- weight packing (fp16), merged into 2 kernels ----------------
// pack_a: Wqkv ([QKVC][DMODEL] gather) + Wo (straight copy)
__global__ void pack_a(const float* __restrict__ Wq, const float* __restrict__ Wk,
                       const float* __restrict__ Wv, const float* __restrict__ Wo,
                       __half* __restrict__ bq, __half* __restrict__ bo) {
    int i = blockIdx.x * blockDim.x + threadIdx.x;
    if (i < QKVC * DMODEL) {
        int n = i >> 9, k = i & 511;
        int sec = n >> 9, h = (n >> 6) & 7, e = n & 63;
        const float* W = (sec == 0) ? Wq : (sec == 1 ? Wk : Wv);
        bq[i] = __float2half(W[((size_t)h * DMODEL + k) * HD + e]);
    } else {
        int j = i - QKVC * DMODEL;
        if (j < DMODEL * DMODEL) bo[j] = __float2half(Wo[j]);
    }
}
// pack_b: W1^T + W2^T  (B[n][k] = W[k][n])
__global__ void pack_b(const float* __restrict__ W1, const float* __restrict__ W2,
                       __half* __restrict__ b1w, __half* __restrict__ b2w) {
    int i = blockIdx.x * blockDim.x + threadIdx.x;
    if (i < DMODEL * DFF) {
        int n = i / DMODEL, k = i - n * DMODEL;     // b1w[n][k], n<DFF, k<DMODEL
        b1w[i] = __float2half(W1[(size_t)k * DFF + n]);
    } else {
        int j = i - DMODEL * DFF;
        if (j < DFF * DMODEL) {
            int n = j / DFF, k = j - n * DFF;       // b2w[n][k], n<DMODEL, k<DFF
            b2w[j] = __float2half(W2[(size_t)k * DMODEL + n]);
        }
    }
}

// ---------------- layernorm -> fp16 ----------------
__global__ void ln_half(const float* __restrict__ x, const float* __restrict__ w,
                        const float* __restrict__ b, __half* __restrict__ hi) {
    int gw = (blockIdx.x * blockDim.x + threadIdx.x) >> 5;
    int lane = threadIdx.x & 31;
    if (gw >= NTOK) return;
    const float4* xp = (const float4*)(x + (size_t)gw * DMODEL);
    float4 v[4];
    float s = 0.f, s2 = 0.f;
#pragma unroll
    for (int i = 0; i < 4; i++) {
        v[i] = xp[lane + 32 * i];
        s  += v[i].x + v[i].y + v[i].z + v[i].w;
        s2 += v[i].x * v[i].x + v[i].y * v[i].y + v[i].z * v[i].z + v[i].w * v[i].w;
    }
#pragma unroll
    for (int o = 16; o > 0; o >>= 1) {
        s  += __shfl_xor_sync(0xffffffffu, s,  o);
        s2 += __shfl_xor_sync(0xffffffffu, s2, o);
    }
    float mean = s * (1.f / DMODEL);
    float var  = s2 * (1.f / DMODEL) - mean * mean;
    float rs = rsqrtf(var + 1e-5f);
    const float4* wp = (const float4*)w;
    const float4* bp = (const float4*)b;
#pragma unroll
    for (int i = 0; i < 4; i++) {
        int idx = lane + 32 * i;
        float4 wv = wp[idx], bv = bp[idx], r;
        r.x = (v[i].x - mean) * rs * wv.x + bv.x;
        r.y = (v[i].y - mean) * rs * wv.y + bv.y;
        r.z = (v[i].z - mean) * rs * wv.z + bv.z;
        r.w = (v[i].w - mean) * rs * wv.w + bv.w;
        __half2 h01 = __floats2half2_rn(r.x, r.y);
        __half2 h23 = __floats2half2_rn(r.z, r.w);
        uint2 ph;
        ph.x = *reinterpret_cast<uint32_t*>(&h01);
        ph.y = *reinterpret_cast<uint32_t*>(&h23);
        *(uint2*)(hi + (size_t)gw * DMODEL + idx * 4) = ph;
    }
}

// ---------------- attention: fp16 K/V smem, low-reg, 2-channel-pass ----------------
__global__ void __launch_bounds__(128, 4)
attn_kernel(const __half* __restrict__ qkv, __half* __restrict__ chi) {
    __shared__ __half Ks[4][CTXT * HD];
    __shared__ __half Vs[4][CTXT * HD];
    int warp = threadIdx.x >> 5, lane = threadIdx.x & 31;
    int pair = blockIdx.x * 4 + warp;
    int b = pair >> 3, h = pair & 7;
    const __half* base = qkv + (size_t)b * CTXT * QKVC + h * HD;
    for (int i = lane; i < CTXT * (HD / 4); i += 32) {
        int t = i >> 4, c = (i & 15) << 2;
        *(uint2*)&Ks[warp][t * HD + c] = *(const uint2*)(base + (size_t)t * QKVC + 512 + c);
        *(uint2*)&Vs[warp][t * HD + c] = *(const uint2*)(base + (size_t)t * QKVC + 1024 + c);
    }
    __syncwarp();

    int t = lane;
    uint32_t q2[32];
    if (t < CTXT) {
#pragma unroll
        for (int c = 0; c < 16; c++) {
            uint2 qq = *(const uint2*)(base + (size_t)t * QKVC + c * 4);
            q2[c * 2] = qq.x; q2[c * 2 + 1] = qq.y;
        }
    } else {
#pragma unroll
        for (int c = 0; c < 32; c++) q2[c] = 0;
    }

    float S[CTXT];
#pragma unroll
    for (int s = 0; s < CTXT; s++) {
        float acc = 0.f;
#pragma unroll
        for (int c2 = 0; c2 < 32; c2++) {
            float2 kf = __half22float2(*reinterpret_cast<__half2*>(&Ks[warp][s * HD + c2 * 2]));
            float2 qf = __half22float2(*reinterpret_cast<__half2*>(&q2[c2]));
            acc = fmaf(qf.x, kf.x, acc);
            acc = fmaf(qf.y, kf.y, acc);
        }
        S[s] = (s <= t) ? acc * 0.125f : -1e30f;
    }
    float m = -1e30f;
#pragma unroll
    for (int s = 0; s < CTXT; s++) m = fmaxf(m, S[s]);
    float sum = 0.f;
#pragma unroll
    for (int s = 0; s < CTXT; s++) { S[s] = __expf(S[s] - m); sum += S[s]; }
    float inv = 1.f / sum;
#pragma unroll
    for (int s = 0; s < CTXT; s++) S[s] *= inv;

    size_t off = (size_t)(b * CTXT + t) * DMODEL + h * HD;
#pragma unroll
    for (int hp = 0; hp < 2; hp++) {
        float o[32];
#pragma unroll
        for (int c = 0; c < 32; c++) o[c] = 0.f;
#pragma unroll
        for (int s = 0; s < CTXT; s++) {
            float p = S[s];
#pragma unroll
            for (int c2 = 0; c2 < 16; c2++) {
                float2 vf = __half22float2(
                    *reinterpret_cast<__half2*>(&Vs[warp][s * HD + hp * 32 + c2 * 2]));
                o[c2 * 2]     = fmaf(p, vf.x, o[c2 * 2]);
                o[c2 * 2 + 1] = fmaf(p, vf.y, o[c2 * 2 + 1]);
            }
        }
        if (t < CTXT) {
#pragma unroll
            for (int c = 0; c < 32; c += 4) {
                __half2 h01 = __floats2half2_rn(o[c], o[c + 1]);
                __half2 h23 = __floats2half2_rn(o[c + 2], o[c + 3]);
                uint2 ph;
                ph.x = *reinterpret_cast<uint32_t*>(&h01);
                ph.y = *reinterpret_cast<uint32_t*>(&h23);
                *(uint2*)(chi + off + hp * 32 + c) = ph;
            }
        }
    }
}

// ---------------- mma.sync single-pass fp16 GEMM, BK=32 (R12 config) ------
// 128x128 CTA tile, BK=32, 3-stage cp.async, 8 warps of 64x32.
// Stage (16KB): A[128][32] @0, B @8192.
// Swizzle: byte = r*64 + ((c ^ ((r>>1)&3))<<4), c = 16B-chunk index 0..3.
// EPI: 0 = fp32 out + bias + res; 1 = relu(acc+bias) -> fp16; 2 = plain fp16 out.
#define STAGE 16384u
#define GSMEM (3 * 16384)

template <int EPI>
__global__ void __launch_bounds__(256, 2)
mma_gemm(const __half* __restrict__ Ahi, const __half* __restrict__ Bh,
         const float* __restrict__ bias, const float* __restrict__ res,
         float* __restrict__ C, __half* __restrict__ Chi, int M, int N, int K) {
    extern __shared__ __align__(128) char smem[];
    uint32_t sb = smem_to_u32(smem);
    int tid = threadIdx.x, lane = tid & 31, wid = tid >> 5;
    int row0 = blockIdx.y * 128, col0 = blockIdx.x * 128;
    int wm = wid & 1, wn = wid >> 1;

    uint32_t dstOff[4];
    const __half* gsrc[4];
#pragma unroll
    for (int it = 0; it < 4; ++it) {
        int idx = ((it & 1) << 8) + tid;
        int r = idx >> 2, c = idx & 3;
        int region = it >> 1;                   // 0 A, 1 B
        dstOff[it] = region * 8192 + r * 64 + ((c ^ ((r >> 1) & 3)) << 4);
        const __half* base = (region == 0) ? Ahi : Bh;
        int rowg = ((region == 0) ? row0 : col0) + r;
        gsrc[it] = base + (size_t)rowg * K + c * 8;
    }

    uint32_t aB[2], bB[2];
    {
        int ra = wm * 64 + (lane & 15);
        int rb = wn * 32 + (lane & 7) + ((lane >> 4) << 3);
#pragma unroll
        for (int kc = 0; kc < 2; ++kc) {
            int ca = kc * 2 + (lane >> 4);
            aB[kc] = sb + ra * 64 + ((ca ^ ((ra >> 1) & 3)) << 4);
            int cb = kc * 2 + ((lane >> 3) & 1);
            bB[kc] = sb + 8192 + rb * 64 + ((cb ^ ((rb >> 1) & 3)) << 4);
        }
    }

    float acc[4][4][4];
#pragma unroll
    for (int i = 0; i < 4; i++)
#pragma unroll
        for (int j = 0; j < 4; j++)
#pragma unroll
            for (int k = 0; k < 4; k++) acc[i][j][k] = 0.f;

    const int T = K >> 5;
#pragma unroll
    for (int it = 0; it < 4; ++it) CP_ASYNC16(sb + dstOff[it], gsrc[it]);
    CP_COMMIT();
#pragma unroll
    for (int it = 0; it < 4; ++it) CP_ASYNC16(sb + STAGE + dstOff[it], gsrc[it] + 32);
    CP_COMMIT();

    for (int t = 0; t < T; ++t) {
        CP_WAIT1();
        __syncthreads();
        if (t + 2 < T) {
            int s2 = (t + 2) % 3;
            size_t ko = (size_t)(t + 2) * 32;
#pragma unroll
            for (int it = 0; it < 4; ++it)
                CP_ASYNC16(sb + s2 * STAGE + dstOff[it], gsrc[it] + ko);
        }
        CP_COMMIT();

        uint32_t so = (uint32_t)(t % 3) * STAGE;
#pragma unroll
        for (int kc = 0; kc < 2; ++kc) {
            uint32_t aA = aB[kc] + so, bA = bB[kc] + so;
            uint32_t aR[16], bR[8];
#pragma unroll
            for (int mf = 0; mf < 4; ++mf)
                ldsm4(aR[mf * 4], aR[mf * 4 + 1], aR[mf * 4 + 2], aR[mf * 4 + 3],
                      aA + mf * 1024);
            ldsm4(bR[0], bR[1], bR[2], bR[3], bA);
            ldsm4(bR[4], bR[5], bR[6], bR[7], bA + 1024);
#pragma unroll
            for (int mf = 0; mf < 4; ++mf)
#pragma unroll
                for (int nf = 0; nf < 4; ++nf)
                    mma16816(acc[mf][nf], aR[mf * 4], aR[mf * 4 + 1], aR[mf * 4 + 2],
                             aR[mf * 4 + 3], bR[(nf >> 1) * 4 + (nf & 1) * 2],
                             bR[(nf >> 1) * 4 + (nf & 1) * 2 + 1]);
        }
    }

    // epilogue
    int m0 = row0 + wm * 64, n0 = col0 + wn * 32;
#pragma unroll
    for (int mf = 0; mf < 4; ++mf) {
#pragma unroll
        for (int nf = 0; nf < 4; ++nf) {
            int r = m0 + mf * 16 + (lane >> 2);
            int cg = n0 + nf * 8 + (lane & 3) * 2;
            float v0 = acc[mf][nf][0], v1 = acc[mf][nf][1];
            float v2 = acc[mf][nf][2], v3 = acc[mf][nf][3];
            if (EPI == 0 || EPI == 1) {
                float b0 = bias[cg], b1v = bias[cg + 1];
                v0 += b0; v1 += b1v; v2 += b0; v3 += b1v;
            }
            if (EPI == 1) {
                v0 = fmaxf(v0, 0.f); v1 = fmaxf(v1, 0.f);
                v2 = fmaxf(v2, 0.f); v3 = fmaxf(v3, 0.f);
                *(__half2*)(Chi + (size_t)r * N + cg) = __floats2half2_rn(v0, v1);
                *(__half2*)(Chi + (size_t)(r + 8) * N + cg) = __floats2half2_rn(v2, v3);
            } else if (EPI == 2) {
                *(__half2*)(Chi + (size_t)r * N + cg) = __floats2half2_rn(v0, v1);
                *(__half2*)(Chi + (size_t)(r + 8) * N + cg) = __floats2half2_rn(v2, v3);
            } else {
                size_t o0 = (size_t)r * N + cg, o1 = (size_t)(r + 8) * N + cg;
                float2 r0 = *(const float2*)(res + o0);
                float2 r1 = *(const float2*)(res + o1);
                v0 += r0.x; v1 += r0.y; v2 += r1.x; v3 += r1.y;
                *(float2*)(C + o0) = make_float2(v0, v1);
                *(float2*)(C + o1) = make_float2(v2, v3);
            }
        }
    }
}

// ---------------- launcher ----------------
extern "C" void kernel_launch(void* const* d_in, const int* in_sizes, int n_in,
                              void* d_out, int out_size) {
    const float* x     = (const float*)d_in[0];
    const float* ln1_w = (const float*)d_in[1];
    const float* ln1_b = (const float*)d_in[2];
    const float* Wq    = (const float*)d_in[3];
    const float* Wk    = (const float*)d_in[4];
    const float* Wv    = (const float*)d_in[5];
    const float* Wo    = (const float*)d_in[6];
    const float* Wo_b  = (const float*)d_in[7];
    const float* ln2_w = (const float*)d_in[8];
    const float* ln2_b = (const float*)d_in[9];
    const float* W1    = (const float*)d_in[10];
    const float* b1    = (const float*)d_in[11];
    const float* W2    = (const float*)d_in[12];
    const float* b2    = (const float*)d_in[13];
    float* out = (float*)d_out;

    float* x2;
    __half *qkvh, *hh, *ch, *uh, *bq, *bo, *b1w, *b2w;
    cudaGetSymbolAddress((void**)&qkvh, g_qkvh);
    cudaGetSymbolAddress((void**)&x2,   g_x2);
    cudaGetSymbolAddress((void**)&hh,   g_hh);
    cudaGetSymbolAddress((void**)&ch,   g_ch);
    cudaGetSymbolAddress((void**)&uh,   g_uh);
    cudaGetSymbolAddress((void**)&bq,   g_bqkv);
    cudaGetSymbolAddress((void**)&bo,   g_bo);
    cudaGetSymbolAddress((void**)&b1w,  g_b1w);
    cudaGetSymbolAddress((void**)&b2w,  g_b2w);

    cudaFuncSetAttribute(mma_gemm<0>, cudaFuncAttributeMaxDynamicSharedMemorySize, GSMEM);
    cudaFuncSetAttribute(mma_gemm<1>, cudaFuncAttributeMaxDynamicSharedMemorySize, GSMEM);
    cudaFuncSetAttribute(mma_gemm<2>, cudaFuncAttributeMaxDynamicSharedMemorySize, GSMEM);

    // 1: pack Wqkv + Wo
    pack_a<<<(QKVC * DMODEL + DMODEL * DMODEL + 255) / 256, 256>>>(Wq, Wk, Wv, Wo, bq, bo);
    // 2: pack W1^T + W2^T
    pack_b<<<(2 * DMODEL * DFF + 255) / 256, 256>>>(W1, W2, b1w, b2w);
    // 3: LN1 -> fp16
    ln_half<<<NTOK / 8, 256>>>(x, ln1_w, ln1_b, hh);
    // 4: qkv = h @ Wqkv   (fp16 out)
    mma_gemm<2><<<dim3(QKVC / 128, NTOK / 128), 256, GSMEM>>>(
        hh, bq, nullptr, nullptr, nullptr, qkvh, NTOK, QKVC, DMODEL);
    // 5: attention -> ctx fp16
    attn_kernel<<<(NB * NH) / 4, 128>>>(qkvh, ch);
    // 6: x2 = x + ctx @ Wo^T + Wo_b      <-- ncu -s 5 -c 1 lands here
    mma_gemm<0><<<dim3(DMODEL / 128, NTOK / 128), 256, GSMEM>>>(
        ch, bo, Wo_b, x, x2, nullptr, NTOK, DMODEL, DMODEL);
    // 7: LN2 -> fp16
    ln_half<<<NTOK / 8, 256>>>(x2, ln2_w, ln2_b, hh);
    // 8: u = relu(h2 @ W1 + b1) -> fp16
    mma_gemm<1><<<dim3(DFF / 128, NTOK / 128), 256, GSMEM>>>(
        hh, b1w, b1, nullptr, nullptr, uh, NTOK, DFF, DMODEL);
    // 9: out = x2 + u @ W2 + b2
    mma_gemm<0><<<dim3(DMODEL / 128, NTOK / 128), 256, GSMEM>>>(
        uh, b2w, b2, x2, out, nullptr, NTOK, DMODEL, DFF);
}